// round 4
// baseline (speedup 1.0000x reference)
#include <cuda_runtime.h>
#include <cuda_fp16.h>
#include <cstdint>
#include <cstddef>

// Problem constants
#define Bb 32
#define Ll 2048
#define Uu 512
#define Hh 8
#define HDd 64
#define NPOS (Bb * Ll)      // 65536
#define MCH 1536            // q|k|v channels (cmax indexing)
#define KVW 1024            // stored channels (k,v only)

// GEMM config: M = positions, N = channels, K = 3*512
#define TM 128
#define TN 256
#define BK 64
#define NCHUNK 24           // 1536 / 64
#define A_BYTES (TM * BK * 2)          // 16384
#define B_BYTES (TN * BK * 2)          // 32768
#define STAGE (A_BYTES + B_BYTES)      // 49152
#define NSTAGE 3

// ---------------------------------------------------------------------------
// Device scratch
// ---------------------------------------------------------------------------
__device__ __align__(16) __half g_Th[(size_t)NPOS * Uu];      // fp16(t), 64MB
__device__ __align__(16) __half g_Wh[(size_t)MCH * MCH];      // fp16 W [m][tau*512+k]
__device__ __align__(16) float  g_Y[(size_t)NPOS * KVW];      // k|v conv out, 256MB
__device__ float g_bias[MCH];
__device__ float g_cmax[Bb * MCH];
__device__ float g_att[Bb * Hh * HDd];

// ---------------------------------------------------------------------------
// Helpers
// ---------------------------------------------------------------------------
__device__ __forceinline__ void cp16(uint32_t dst, const void* src, bool valid) {
    int sz = valid ? 16 : 0;
    asm volatile("cp.async.cg.shared.global [%0], [%1], 16, %2;\n"
                 :: "r"(dst), "l"(src), "r"(sz));
}
#define CP_COMMIT() asm volatile("cp.async.commit_group;" ::: "memory")
#define CP_WAIT(n)  asm volatile("cp.async.wait_group %0;" :: "n"(n) : "memory")

__device__ __forceinline__ uint32_t su32(const void* p) {
    uint32_t a;
    asm("{ .reg .u64 t; cvta.to.shared.u64 t, %1; cvt.u32.u64 %0, t; }" : "=r"(a) : "l"(p));
    return a;
}

__device__ __forceinline__ void mma_f16(float c[4],
                                        uint32_t a0, uint32_t a1, uint32_t a2, uint32_t a3,
                                        uint32_t b0, uint32_t b1) {
    asm volatile(
        "mma.sync.aligned.m16n8k16.row.col.f32.f16.f16.f32 "
        "{%0,%1,%2,%3}, {%4,%5,%6,%7}, {%8,%9}, {%0,%1,%2,%3};\n"
        : "+f"(c[0]), "+f"(c[1]), "+f"(c[2]), "+f"(c[3])
        : "r"(a0), "r"(a1), "r"(a2), "r"(a3), "r"(b0), "r"(b1));
}

#define LDSM_X4(r0, r1, r2, r3, addr)                                         \
    asm volatile("ldmatrix.sync.aligned.m8n8.x4.shared.b16 {%0,%1,%2,%3}, [%4];" \
                 : "=r"(r0), "=r"(r1), "=r"(r2), "=r"(r3) : "r"(addr))

__device__ __forceinline__ void atomicMaxF(float* a, float v) {
    if (v >= 0.f) atomicMax((int*)a, __float_as_int(v));
    else          atomicMin((unsigned*)a, __float_as_uint(v));
}

// ---------------------------------------------------------------------------
// t -> fp16
// ---------------------------------------------------------------------------
__global__ void tconv_kernel(const float* __restrict__ t) {
    size_t gid = (size_t)blockIdx.x * blockDim.x + threadIdx.x;   // float4 index
    if (gid >= (size_t)NPOS * Uu / 4) return;
    float4 v = ((const float4*)t)[gid];
    __half2 h0 = __floats2half2_rn(v.x, v.y);
    __half2 h1 = __floats2half2_rn(v.z, v.w);
    ((uint2*)g_Th)[gid] = make_uint2(*(uint32_t*)&h0, *(uint32_t*)&h1);
}

// ---------------------------------------------------------------------------
// weights -> fp16 [m][tau*512+k] (K-major rows), bias
// ---------------------------------------------------------------------------
__global__ void repack_kernel(const float* __restrict__ Wq, const float* __restrict__ bq,
                              const float* __restrict__ Wk, const float* __restrict__ bk,
                              const float* __restrict__ Wv, const float* __restrict__ bv) {
    int gid = blockIdx.x * blockDim.x + threadIdx.x;
    if (gid < MCH)
        g_bias[gid] = gid < 512 ? bq[gid] : (gid < 1024 ? bk[gid - 512] : bv[gid - 1024]);
    if (gid >= MCH * MCH) return;
    int mg   = gid / MCH;
    int kk   = gid % MCH;
    int tau  = kk / 512;
    int k    = kk % 512;
    int conv = mg / 512;
    int m    = mg % 512;
    const float* W = (conv == 0) ? Wq : ((conv == 1) ? Wk : Wv);
    g_Wh[gid] = __float2half_rn(W[m * 1536 + k * 3 + tau]);
}

__global__ void cmax_init_kernel() {
    int gid = blockIdx.x * blockDim.x + threadIdx.x;
    if (gid < Bb * MCH) ((unsigned*)g_cmax)[gid] = 0xff800000u;   // -inf
}

// ---------------------------------------------------------------------------
// fused qkv conv: fp16 HMMA GEMM, 128x256 CTA tile, 64x64 warp tile,
// 3-stage cp.async pipeline, ldmatrix fragment loads.
// Epilogue: +bias, per-channel max -> g_cmax, store k/v rows to g_Y.
// ---------------------------------------------------------------------------
__global__ __launch_bounds__(256, 1) void conv_hmma_kernel() {
    extern __shared__ __align__(128) char dsmem[];   // 3 * 48KB
    __shared__ float bias_s[TN];

    const int tid  = threadIdx.x;
    const int wid  = tid >> 5;
    const int lane = tid & 31;
    const int g    = lane >> 2;
    const int tg   = lane & 3;
    const int wm   = wid & 1;           // 2 warps over M (64 rows each)
    const int wn   = wid >> 1;          // 4 warps over N (64 cols each)
    const int m0   = blockIdx.x * TN;
    const int n0   = blockIdx.y * TM;
    const int b    = n0 >> 11;
    const int l0   = n0 & 2047;

    bias_s[tid] = g_bias[m0 + tid];

    const uint32_t smem0 = su32(dsmem);

    // ---- chunk loader (256 threads) ----
    auto load_chunk = [&](int c, int slot) {
        const int tau = c >> 3;
        const int k0  = (c & 7) * BK;
        const uint32_t abase = smem0 + (uint32_t)slot * STAGE;
        const uint32_t bbase = abase + A_BYTES;
#pragma unroll
        for (int p = 0; p < 4; p++) {           // A: 128 rows x 8 chunks
            int idx = p * 256 + tid;
            int row = idx >> 3;
            int j   = idx & 7;
            int l   = l0 + row + tau - 1;
            bool ok = (l >= 0 && l < Ll);
            const void* src = g_Th + ((size_t)(b * Ll + (ok ? l : 0))) * Uu + k0 + j * 8;
            cp16(abase + (uint32_t)(row * 128 + ((j ^ (row & 7)) << 4)), src, ok);
        }
#pragma unroll
        for (int p = 0; p < 8; p++) {           // B: 256 rows x 8 chunks
            int idx = p * 256 + tid;
            int row = idx >> 3;
            int j   = idx & 7;
            const void* src = g_Wh + (size_t)(m0 + row) * MCH + tau * 512 + k0 + j * 8;
            cp16(bbase + (uint32_t)(row * 128 + ((j ^ (row & 7)) << 4)), src, true);
        }
    };

    // ldmatrix per-lane row offsets (mask for swizzle is lane&7 since all
    // row bases are multiples of 16)
    const int sub = lane >> 3;          // 0..3: 8x8 tile index inside x4
    const int lr  = lane & 7;
    uint32_t aRowOff[4], bRowOff[4];
#pragma unroll
    for (int mf = 0; mf < 4; mf++)
        aRowOff[mf] = (uint32_t)((wm * 64 + mf * 16 + ((sub & 1) << 3) + lr) * 128);
#pragma unroll
    for (int p = 0; p < 4; p++)
        bRowOff[p] = (uint32_t)((wn * 64 + p * 16 + ((sub >> 1) << 3) + lr) * 128);
    const int aSub = sub >> 1;          // A: chunk select bit
    const int bSub = sub & 1;           // B: chunk select bit

    float acc[4][8][4];
#pragma unroll
    for (int i = 0; i < 4; i++)
#pragma unroll
        for (int j = 0; j < 8; j++)
#pragma unroll
            for (int e = 0; e < 4; e++) acc[i][j][e] = 0.f;

    // prologue
    load_chunk(0, 0); CP_COMMIT();
    load_chunk(1, 1); CP_COMMIT();

    for (int i = 0; i < NCHUNK; i++) {
        if (i + 1 < NCHUNK) { CP_WAIT(1); } else { CP_WAIT(0); }
        __syncthreads();
        if (i + 2 < NCHUNK) { load_chunk(i + 2, (i + 2) % NSTAGE); CP_COMMIT(); }

        const uint32_t abase = smem0 + (uint32_t)(i % NSTAGE) * STAGE;
        const uint32_t bbase = abase + A_BYTES;
#pragma unroll
        for (int kk = 0; kk < 4; kk++) {
            const uint32_t aCh = (uint32_t)(((2 * kk + aSub) ^ lr) << 4);
            const uint32_t bCh = (uint32_t)(((2 * kk + bSub) ^ lr) << 4);
            uint32_t a[4][4];
#pragma unroll
            for (int mf = 0; mf < 4; mf++)
                LDSM_X4(a[mf][0], a[mf][1], a[mf][2], a[mf][3],
                        abase + aRowOff[mf] + aCh);
            uint32_t bf[8][2];
#pragma unroll
            for (int p = 0; p < 4; p++)
                LDSM_X4(bf[2 * p][0], bf[2 * p][1], bf[2 * p + 1][0], bf[2 * p + 1][1],
                        bbase + bRowOff[p] + bCh);
#pragma unroll
            for (int mf = 0; mf < 4; mf++)
#pragma unroll
                for (int nf = 0; nf < 8; nf++)
                    mma_f16(acc[mf][nf], a[mf][0], a[mf][1], a[mf][2], a[mf][3],
                            bf[nf][0], bf[nf][1]);
        }
    }

    // ---- epilogue: bias, store k/v, channel max ----
    const bool do_store = (m0 >= 512);
#pragma unroll
    for (int nf = 0; nf < 8; nf++) {
        const int col = m0 + wn * 64 + nf * 8 + 2 * tg;
        const float b0 = bias_s[col - m0], b1 = bias_s[col - m0 + 1];
        float cm0 = -3.4e38f, cm1 = -3.4e38f;
#pragma unroll
        for (int mf = 0; mf < 4; mf++) {
            float v0 = acc[mf][nf][0] + b0;
            float v1 = acc[mf][nf][1] + b1;
            float v2 = acc[mf][nf][2] + b0;
            float v3 = acc[mf][nf][3] + b1;
            if (do_store) {
                size_t n = (size_t)n0 + wm * 64 + mf * 16 + g;
                float* p = g_Y + n * KVW + (col - 512);
                *(float2*)p = make_float2(v0, v1);
                *(float2*)(p + (size_t)8 * KVW) = make_float2(v2, v3);
            }
            cm0 = fmaxf(cm0, fmaxf(v0, v2));
            cm1 = fmaxf(cm1, fmaxf(v1, v3));
        }
#pragma unroll
        for (int o = 4; o <= 16; o <<= 1) {
            cm0 = fmaxf(cm0, __shfl_xor_sync(0xffffffffu, cm0, o));
            cm1 = fmaxf(cm1, __shfl_xor_sync(0xffffffffu, cm1, o));
        }
        if (lane < 4) {
            atomicMaxF(&g_cmax[b * MCH + col], cm0);
            atomicMaxF(&g_cmax[b * MCH + col + 1], cm1);
        }
    }
}

// ---------------------------------------------------------------------------
// attention per (b, h): 2049 keys = [global max key, maxpool3 keys]
// g_Y layout: [n][1024], K cols 0..511, V cols 512..1023
// ---------------------------------------------------------------------------
__global__ __launch_bounds__(512) void attn_kernel(const int* __restrict__ gmask,
                                                   const int* __restrict__ tmask) {
    __shared__ float q_s[64];
    __shared__ float lg[2049];
    __shared__ float red[512];

    const int bh   = blockIdx.x;
    const int b    = bh >> 3;
    const int h    = bh & 7;
    const int tid  = threadIdx.x;
    const int lane = tid & 31;
    const int w    = tid >> 5;          // 0..15

    if (tid < 64) q_s[tid] = g_cmax[b * MCH + h * HDd + tid];
    __syncthreads();

    const float scale = 0.04419417382415922f;   // 1/sqrt(512)
    const float gmf   = (float)gmask[b];

    const float* Yk = g_Y + (size_t)b * Ll * KVW + h * HDd;

    // logits (warp per key)
    for (int j = w; j <= Ll; j += 16) {
        float k1, k2;
        if (j == 0) {
            k1 = g_cmax[b * MCH + 512 + h * HDd + lane];
            k2 = g_cmax[b * MCH + 512 + h * HDd + lane + 32];
        } else {
            int l = j - 1;
            const float* r = Yk + (size_t)l * KVW;
            k1 = r[lane];
            k2 = r[lane + 32];
            if (l > 0)      { k1 = fmaxf(k1, r[lane - KVW]);     k2 = fmaxf(k2, r[lane + 32 - KVW]); }
            if (l < Ll - 1) { k1 = fmaxf(k1, r[lane + KVW]);     k2 = fmaxf(k2, r[lane + 32 + KVW]); }
        }
        float p = q_s[lane] * k1 + q_s[lane + 32] * k2;
#pragma unroll
        for (int o = 16; o; o >>= 1) p += __shfl_down_sync(0xffffffffu, p, o);
        if (lane == 0) {
            int mk = (j == 0) ? gmask[b] : tmask[b * Ll + (j - 1)];
            lg[j] = mk ? p * scale : -1e30f;
        }
    }
    __syncthreads();

    // softmax max
    float lm = -1e30f;
    for (int j = tid; j < Ll + 1; j += 512) lm = fmaxf(lm, lg[j]);
    red[tid] = lm;
    __syncthreads();
    for (int s = 256; s; s >>= 1) {
        if (tid < s) red[tid] = fmaxf(red[tid], red[tid + s]);
        __syncthreads();
    }
    float mx = red[0];
    __syncthreads();

    // exp + sum
    float ls = 0.f;
    for (int j = tid; j < Ll + 1; j += 512) {
        float e = expf(lg[j] - mx);
        lg[j] = e;
        ls += e;
    }
    red[tid] = ls;
    __syncthreads();
    for (int s = 256; s; s >>= 1) {
        if (tid < s) red[tid] += red[tid + s];
        __syncthreads();
    }
    float sinv = 1.0f / red[0];
    __syncthreads();

    // weighted sum over values (maxpool3 on the fly), 8 groups of 64
    const int d   = tid & 63;
    const int grp = tid >> 6;
    const float* Yv = g_Y + (size_t)b * Ll * KVW + 512 + h * HDd + d;
    float acc = 0.f;
    for (int j = grp; j <= Ll; j += 8) {
        float v;
        if (j == 0) {
            v = g_cmax[b * MCH + 1024 + h * HDd + d];
        } else {
            int l = j - 1;
            const float* r = Yv + (size_t)l * KVW;
            v = r[0];
            if (l > 0)      v = fmaxf(v, r[-KVW]);
            if (l < Ll - 1) v = fmaxf(v, r[KVW]);
        }
        acc += lg[j] * v;
    }
    red[tid] = acc;
    __syncthreads();
    if (tid < 64) {
        float o = 0.f;
#pragma unroll
        for (int k = 0; k < 8; k++) o += red[tid + 64 * k];
        g_att[(b * Hh + h) * HDd + tid] = o * sinv * gmf;
    }
}

// ---------------------------------------------------------------------------
// head-mix (Wh 8x8) + output 1x1 conv (Wo 512x512)
// ---------------------------------------------------------------------------
__global__ __launch_bounds__(512) void final_kernel(const float* __restrict__ Wh,
                                                    const float* __restrict__ bh,
                                                    const float* __restrict__ Wo,
                                                    const float* __restrict__ bo,
                                                    float* __restrict__ out) {
    const int b   = blockIdx.x;
    const int tid = threadIdx.x;
    __shared__ float mid[512];

    const int oh = tid >> 6;
    const int d  = tid & 63;
    float s = bh[oh];
#pragma unroll
    for (int i = 0; i < 8; i++) s += Wh[oh * 8 + i] * g_att[(b * Hh + i) * HDd + d];
    mid[tid] = s;
    __syncthreads();

    float o = bo[tid];
    const float* wr = Wo + (size_t)tid * 512;
#pragma unroll 8
    for (int i = 0; i < 512; i++) o += wr[i] * mid[i];
    out[b * 512 + tid] = o;
}

// ---------------------------------------------------------------------------
// Launch
// ---------------------------------------------------------------------------
extern "C" void kernel_launch(void* const* d_in, const int* in_sizes, int n_in,
                              void* d_out, int out_size) {
    const float* t     = (const float*)d_in[0];
    const int*   gmask = (const int*)d_in[2];
    const int*   tmask = (const int*)d_in[3];
    const float* Wq    = (const float*)d_in[4];
    const float* bq    = (const float*)d_in[5];
    const float* Wk    = (const float*)d_in[6];
    const float* bk    = (const float*)d_in[7];
    const float* Wv    = (const float*)d_in[8];
    const float* bv    = (const float*)d_in[9];
    const float* Wh    = (const float*)d_in[10];
    const float* bh    = (const float*)d_in[11];
    const float* Wo    = (const float*)d_in[12];
    const float* bo    = (const float*)d_in[13];
    float* out = (float*)d_out;

    cudaFuncSetAttribute(conv_hmma_kernel, cudaFuncAttributeMaxDynamicSharedMemorySize,
                         NSTAGE * STAGE);

    tconv_kernel<<<(int)(((size_t)NPOS * Uu / 4 + 255) / 256), 256>>>(t);
    repack_kernel<<<(MCH * MCH + 255) / 256, 256>>>(Wq, bq, Wk, bk, Wv, bv);
    cmax_init_kernel<<<(Bb * MCH + 255) / 256, 256>>>();
    conv_hmma_kernel<<<dim3(MCH / TN, NPOS / TM), 256, NSTAGE * STAGE>>>();
    attn_kernel<<<Bb * Hh, 512>>>(gmask, tmask);
    final_kernel<<<Bb, 512>>>(Wh, bh, Wo, bo, out);
}

// round 5
// speedup vs baseline: 1.1965x; 1.1965x over previous
#include <cuda_runtime.h>
#include <cuda_fp16.h>
#include <cstdint>
#include <cstddef>

// Problem constants
#define Bb 32
#define Ll 2048
#define Uu 512
#define Hh 8
#define HDd 64
#define NPOS (Bb * Ll)      // 65536
#define MCH 1536            // q|k|v channels (cmax indexing)
#define KVW 1024            // stored channels (k,v only), fp16
#define LGS 2049            // logits per (b,h)
#define NSL 8               // attention slices

// GEMM config: M = positions, N = channels, K = 3*512
#define TM 128
#define TN 128
#define BK 64
#define NCHUNK 24           // 1536 / 64
#define STAGE 32768         // 16KB A + 16KB B
#define NSTAGE 3

// ---------------------------------------------------------------------------
// Device scratch
// ---------------------------------------------------------------------------
__device__ __align__(16) __half g_Th[(size_t)NPOS * Uu];      // fp16(t), 64MB
__device__ __align__(16) __half g_Wh[(size_t)MCH * MCH];      // fp16 W [m][tau*512+k]
__device__ __align__(16) __half g_Yh[(size_t)NPOS * KVW];     // k|v conv out fp16, 128MB
__device__ float g_bias[MCH];
__device__ float g_cmax[Bb * MCH];
__device__ float g_lg[Bb * Hh * LGS];                         // logits -> probs
__device__ float g_part[Bb * Hh * NSL * HDd];                 // V partial sums

// ---------------------------------------------------------------------------
// Helpers
// ---------------------------------------------------------------------------
__device__ __forceinline__ void cp16(uint32_t dst, const void* src, bool valid) {
    int sz = valid ? 16 : 0;
    asm volatile("cp.async.cg.shared.global [%0], [%1], 16, %2;\n"
                 :: "r"(dst), "l"(src), "r"(sz));
}
#define CP_COMMIT() asm volatile("cp.async.commit_group;" ::: "memory")
#define CP_WAIT(n)  asm volatile("cp.async.wait_group %0;" :: "n"(n) : "memory")

__device__ __forceinline__ uint32_t su32(const void* p) {
    uint32_t a;
    asm("{ .reg .u64 t; cvta.to.shared.u64 t, %1; cvt.u32.u64 %0, t; }" : "=r"(a) : "l"(p));
    return a;
}

__device__ __forceinline__ void mma_f16(float c[4],
                                        uint32_t a0, uint32_t a1, uint32_t a2, uint32_t a3,
                                        uint32_t b0, uint32_t b1) {
    asm volatile(
        "mma.sync.aligned.m16n8k16.row.col.f32.f16.f16.f32 "
        "{%0,%1,%2,%3}, {%4,%5,%6,%7}, {%8,%9}, {%0,%1,%2,%3};\n"
        : "+f"(c[0]), "+f"(c[1]), "+f"(c[2]), "+f"(c[3])
        : "r"(a0), "r"(a1), "r"(a2), "r"(a3), "r"(b0), "r"(b1));
}

__device__ __forceinline__ void atomicMaxF(float* a, float v) {
    if (v >= 0.f) atomicMax((int*)a, __float_as_int(v));
    else          atomicMin((unsigned*)a, __float_as_uint(v));
}

// fragment LDS from a swizzled tile: row stride 128B, 16B-chunk XOR (row&7)
__device__ __forceinline__ uint32_t lds_frag(const char* base, int row, int h) {
    int chunk = h >> 3;
    int off   = (h & 7) * 2;
    return *(const uint32_t*)(base + row * 128 + ((chunk ^ (row & 7)) << 4) + off);
}

// ---------------------------------------------------------------------------
// t -> fp16
// ---------------------------------------------------------------------------
__global__ void tconv_kernel(const float* __restrict__ t) {
    size_t gid = (size_t)blockIdx.x * blockDim.x + threadIdx.x;   // float4 index
    if (gid >= (size_t)NPOS * Uu / 4) return;
    float4 v = ((const float4*)t)[gid];
    __half2 h0 = __floats2half2_rn(v.x, v.y);
    __half2 h1 = __floats2half2_rn(v.z, v.w);
    ((uint2*)g_Th)[gid] = make_uint2(*(uint32_t*)&h0, *(uint32_t*)&h1);
}

// ---------------------------------------------------------------------------
// weights -> fp16 [m][tau*512+k] (K-major rows), bias
// ---------------------------------------------------------------------------
__global__ void repack_kernel(const float* __restrict__ Wq, const float* __restrict__ bq,
                              const float* __restrict__ Wk, const float* __restrict__ bk,
                              const float* __restrict__ Wv, const float* __restrict__ bv) {
    int gid = blockIdx.x * blockDim.x + threadIdx.x;
    if (gid < MCH)
        g_bias[gid] = gid < 512 ? bq[gid] : (gid < 1024 ? bk[gid - 512] : bv[gid - 1024]);
    if (gid >= MCH * MCH) return;
    int mg   = gid / MCH;
    int kk   = gid % MCH;
    int tau  = kk / 512;
    int k    = kk % 512;
    int conv = mg / 512;
    int m    = mg % 512;
    const float* W = (conv == 0) ? Wq : ((conv == 1) ? Wk : Wv);
    g_Wh[gid] = __float2half_rn(W[m * 1536 + k * 3 + tau]);
}

__global__ void cmax_init_kernel() {
    int gid = blockIdx.x * blockDim.x + threadIdx.x;
    if (gid < Bb * MCH) ((unsigned*)g_cmax)[gid] = 0xff800000u;   // -inf
}

// ---------------------------------------------------------------------------
// fused qkv conv: fp16 HMMA GEMM, 128x128 tile, 3-stage cp.async pipeline
// (round-3 measured-best config). Epilogue: +bias, channel max, fp16 k/v store.
// ---------------------------------------------------------------------------
__global__ __launch_bounds__(256, 2) void conv_hmma_kernel() {
    extern __shared__ __align__(128) char dsmem[];   // 3 * 32KB
    __shared__ float bias_s[TN];

    const int tid  = threadIdx.x;
    const int wid  = tid >> 5;
    const int lane = tid & 31;
    const int g    = lane >> 2;
    const int tg   = lane & 3;
    const int wm   = wid >> 1;          // 0..3: M strip of 32
    const int wn   = wid & 1;           // 0..1: N strip of 64
    const int m0   = blockIdx.x * TN;
    const int n0   = blockIdx.y * TM;
    const int b    = n0 >> 11;
    const int l0   = n0 & 2047;

    if (tid < TN) bias_s[tid] = g_bias[m0 + tid];

    const uint32_t smem0 = su32(dsmem);

    auto load_chunk = [&](int c, int slot) {
        const int tau = c >> 3;
        const int k0  = (c & 7) * BK;
        const uint32_t abase = smem0 + (uint32_t)slot * STAGE;
        const uint32_t bbase = abase + 16384u;
#pragma unroll
        for (int p = 0; p < 4; p++) {
            int idx = p * 256 + tid;       // 0..1023
            int row = idx >> 3;
            int j   = idx & 7;
            int l   = l0 + row + tau - 1;
            bool ok = (l >= 0 && l < Ll);
            const void* src = g_Th + ((size_t)(b * Ll + (ok ? l : 0))) * Uu + k0 + j * 8;
            cp16(abase + (uint32_t)(row * 128 + ((j ^ (row & 7)) << 4)), src, ok);
        }
#pragma unroll
        for (int p = 0; p < 4; p++) {
            int idx = p * 256 + tid;
            int row = idx >> 3;
            int j   = idx & 7;
            const void* src = g_Wh + (size_t)(m0 + row) * MCH + tau * 512 + k0 + j * 8;
            cp16(bbase + (uint32_t)(row * 128 + ((j ^ (row & 7)) << 4)), src, true);
        }
    };

    float acc[2][8][4];
#pragma unroll
    for (int i = 0; i < 2; i++)
#pragma unroll
        for (int j = 0; j < 8; j++)
#pragma unroll
            for (int e = 0; e < 4; e++) acc[i][j][e] = 0.f;

    load_chunk(0, 0); CP_COMMIT();
    load_chunk(1, 1); CP_COMMIT();

    for (int i = 0; i < NCHUNK; i++) {
        if (i + 1 < NCHUNK) { CP_WAIT(1); } else { CP_WAIT(0); }
        __syncthreads();
        if (i + 2 < NCHUNK) { load_chunk(i + 2, (i + 2) % NSTAGE); CP_COMMIT(); }

        const char* Ab   = dsmem + (i % NSTAGE) * STAGE;
        const char* Bbse = Ab + 16384;
#pragma unroll
        for (int kk = 0; kk < 4; kk++) {
            const int kb = kk * 16;
            uint32_t a[2][4];
#pragma unroll
            for (int mf = 0; mf < 2; mf++) {
                int r0 = wm * 32 + mf * 16 + g;
                a[mf][0] = lds_frag(Ab, r0,     kb + 2 * tg);
                a[mf][1] = lds_frag(Ab, r0 + 8, kb + 2 * tg);
                a[mf][2] = lds_frag(Ab, r0,     kb + 8 + 2 * tg);
                a[mf][3] = lds_frag(Ab, r0 + 8, kb + 8 + 2 * tg);
            }
            uint32_t bf[8][2];
#pragma unroll
            for (int nf = 0; nf < 8; nf++) {
                int rn = wn * 64 + nf * 8 + g;
                bf[nf][0] = lds_frag(Bbse, rn, kb + 2 * tg);
                bf[nf][1] = lds_frag(Bbse, rn, kb + 8 + 2 * tg);
            }
#pragma unroll
            for (int mf = 0; mf < 2; mf++)
#pragma unroll
                for (int nf = 0; nf < 8; nf++)
                    mma_f16(acc[mf][nf], a[mf][0], a[mf][1], a[mf][2], a[mf][3],
                            bf[nf][0], bf[nf][1]);
        }
    }

    // ---- epilogue: bias, channel max, fp16 k/v store ----
    const bool do_store = (m0 >= 512);
#pragma unroll
    for (int nf = 0; nf < 8; nf++) {
        const int col = m0 + wn * 64 + nf * 8 + 2 * tg;
        const float b0 = bias_s[col - m0], b1 = bias_s[col - m0 + 1];
        float cm0 = -3.4e38f, cm1 = -3.4e38f;
#pragma unroll
        for (int mf = 0; mf < 2; mf++) {
            float v0 = acc[mf][nf][0] + b0;
            float v1 = acc[mf][nf][1] + b1;
            float v2 = acc[mf][nf][2] + b0;
            float v3 = acc[mf][nf][3] + b1;
            if (do_store) {
                size_t n = (size_t)n0 + wm * 32 + mf * 16 + g;
                __half2* p = (__half2*)(g_Yh + n * KVW + (col - 512));
                *p = __floats2half2_rn(v0, v1);
                *(__half2*)((char*)p + (size_t)8 * KVW * 2) = __floats2half2_rn(v2, v3);
            }
            cm0 = fmaxf(cm0, fmaxf(v0, v2));
            cm1 = fmaxf(cm1, fmaxf(v1, v3));
        }
#pragma unroll
        for (int o = 4; o <= 16; o <<= 1) {
            cm0 = fmaxf(cm0, __shfl_xor_sync(0xffffffffu, cm0, o));
            cm1 = fmaxf(cm1, __shfl_xor_sync(0xffffffffu, cm1, o));
        }
        if (lane < 4) {
            atomicMaxF(&g_cmax[b * MCH + col], cm0);
            atomicMaxF(&g_cmax[b * MCH + col + 1], cm1);
        }
    }
}

// ---------------------------------------------------------------------------
// attention stage 1: raw masked logits. grid = 32*8*8 (b, h, slice).
// keys: j=0 global max key, j>=1 maxpool3(k)[j-1]
// ---------------------------------------------------------------------------
__global__ __launch_bounds__(256) void logits_kernel(const int* __restrict__ gmask,
                                                     const int* __restrict__ tmask) {
    __shared__ float q_s[64];
    const int bid   = blockIdx.x;
    const int slice = bid & 7;
    const int h     = (bid >> 3) & 7;
    const int b     = bid >> 6;
    const int tid   = threadIdx.x;
    const int lane  = tid & 31;
    const int w     = tid >> 5;

    if (tid < 64) q_s[tid] = g_cmax[b * MCH + h * HDd + tid];
    __syncthreads();

    const float scale = 0.04419417382415922f;   // 1/sqrt(512)
    const int j0  = slice * 256;
    const int cnt = (slice == NSL - 1) ? 257 : 256;
    const __half* Yk = g_Yh + (size_t)b * Ll * KVW + h * HDd;
    float* lg = g_lg + (b * Hh + h) * LGS;

    for (int jj = w; jj < cnt; jj += 8) {
        const int j = j0 + jj;
        float k0f, k1f;
        if (j == 0) {
            k0f = g_cmax[b * MCH + 512 + h * HDd + 2 * lane];
            k1f = g_cmax[b * MCH + 512 + h * HDd + 2 * lane + 1];
        } else {
            int l = j - 1;
            const __half2* r = (const __half2*)(Yk + (size_t)l * KVW) + lane;
            __half2 kv = r[0];
            if (l > 0)      kv = __hmax2(kv, r[-(KVW / 2)]);
            if (l < Ll - 1) kv = __hmax2(kv, r[KVW / 2]);
            float2 kf = __half22float2(kv);
            k0f = kf.x; k1f = kf.y;
        }
        float p = q_s[2 * lane] * k0f + q_s[2 * lane + 1] * k1f;
#pragma unroll
        for (int o = 16; o; o >>= 1) p += __shfl_down_sync(0xffffffffu, p, o);
        if (lane == 0) {
            int mk = (j == 0) ? gmask[b] : tmask[b * Ll + (j - 1)];
            lg[j] = mk ? p * scale : -1e30f;
        }
    }
}

// ---------------------------------------------------------------------------
// attention stage 2: softmax in place, probs scaled by 1/sum and g_mask.
// grid = 256 (b, h)
// ---------------------------------------------------------------------------
__global__ __launch_bounds__(256) void softmax_kernel(const int* __restrict__ gmask) {
    __shared__ float red[256];
    const int b   = blockIdx.x >> 3;
    const int h   = blockIdx.x & 7;
    const int tid = threadIdx.x;
    float* lg = g_lg + (b * Hh + h) * LGS;

    float lm = -1e30f;
    for (int j = tid; j < LGS; j += 256) lm = fmaxf(lm, lg[j]);
    red[tid] = lm;
    __syncthreads();
    for (int s = 128; s; s >>= 1) {
        if (tid < s) red[tid] = fmaxf(red[tid], red[tid + s]);
        __syncthreads();
    }
    const float mx = red[0];
    __syncthreads();

    float ls = 0.f;
    float ev[9];
    int nv = 0;
    for (int j = tid; j < LGS; j += 256) {
        float e = expf(lg[j] - mx);
        ev[nv++] = e;
        ls += e;
    }
    red[tid] = ls;
    __syncthreads();
    for (int s = 128; s; s >>= 1) {
        if (tid < s) red[tid] += red[tid + s];
        __syncthreads();
    }
    const float fac = (1.0f / red[0]) * (float)gmask[b];
    nv = 0;
    for (int j = tid; j < LGS; j += 256) lg[j] = ev[nv++] * fac;
}

// ---------------------------------------------------------------------------
// attention stage 3: weighted V sum partials. grid = 32*8*8 (b, h, slice)
// ---------------------------------------------------------------------------
__global__ __launch_bounds__(256) void vsum_kernel() {
    __shared__ float red[256];
    const int bid   = blockIdx.x;
    const int slice = bid & 7;
    const int h     = (bid >> 3) & 7;
    const int b     = bid >> 6;
    const int tid   = threadIdx.x;
    const int d     = tid & 63;
    const int grp   = tid >> 6;

    const int j0  = slice * 256;
    const int cnt = (slice == NSL - 1) ? 257 : 256;
    const __half* Yv = g_Yh + (size_t)b * Ll * KVW + 512 + h * HDd + d;
    const float* lg = g_lg + (b * Hh + h) * LGS;

    float acc = 0.f;
    for (int jj = grp; jj < cnt; jj += 4) {
        const int j = j0 + jj;
        float v;
        if (j == 0) {
            v = g_cmax[b * MCH + 1024 + h * HDd + d];
        } else {
            int l = j - 1;
            const __half* r = Yv + (size_t)l * KVW;
            __half hv = r[0];
            if (l > 0)      hv = __hmax(hv, r[-KVW]);
            if (l < Ll - 1) hv = __hmax(hv, r[KVW]);
            v = __half2float(hv);
        }
        acc += lg[j] * v;
    }
    red[tid] = acc;
    __syncthreads();
    if (tid < 64) {
        float o = red[tid] + red[tid + 64] + red[tid + 128] + red[tid + 192];
        g_part[((b * Hh + h) * NSL + slice) * HDd + d] = o;
    }
}

// ---------------------------------------------------------------------------
// final: reduce slice partials, head-mix (Wh 8x8), output 1x1 conv (Wo).
// grid = (32 batches, 4 output quarters), 512 threads.
// ---------------------------------------------------------------------------
__global__ __launch_bounds__(512) void final_kernel(const float* __restrict__ Wh,
                                                    const float* __restrict__ bh,
                                                    const float* __restrict__ Wo,
                                                    const float* __restrict__ bo,
                                                    float* __restrict__ out) {
    const int b    = blockIdx.x;
    const int quad = blockIdx.y;
    const int tid  = threadIdx.x;
    __shared__ float att_s[512];   // (h, d)
    __shared__ float mid[512];

    // reduce slice partials -> att[h][d]
    {
        const int h = tid >> 6, d = tid & 63;
        const float* p = g_part + ((b * Hh + h) * NSL) * HDd + d;
        float s = 0.f;
#pragma unroll
        for (int sl = 0; sl < NSL; sl++) s += p[sl * HDd];
        att_s[tid] = s;
    }
    __syncthreads();

    // head mix: mid[oh*64+d] = bh[oh] + sum_i Wh[oh,i]*att[i][d]
    {
        const int oh = tid >> 6, d = tid & 63;
        float s = bh[oh];
#pragma unroll
        for (int i = 0; i < 8; i++) s += Wh[oh * 8 + i] * att_s[i * HDd + d];
        mid[tid] = s;
    }
    __syncthreads();

    // output conv: 128 channels per block, 4 threads per channel
    const int o    = quad * 128 + (tid >> 2);
    const int part = tid & 3;
    const float* wr = Wo + (size_t)o * 512 + part * 128;
    const float* mr = mid + part * 128;
    float s = 0.f;
#pragma unroll 16
    for (int i = 0; i < 128; i++) s += wr[i] * mr[i];
    s += __shfl_xor_sync(0xffffffffu, s, 1);
    s += __shfl_xor_sync(0xffffffffu, s, 2);
    if (part == 0) out[b * 512 + o] = s + bo[o];
}

// ---------------------------------------------------------------------------
// Launch
// ---------------------------------------------------------------------------
extern "C" void kernel_launch(void* const* d_in, const int* in_sizes, int n_in,
                              void* d_out, int out_size) {
    const float* t     = (const float*)d_in[0];
    const int*   gmask = (const int*)d_in[2];
    const int*   tmask = (const int*)d_in[3];
    const float* Wq    = (const float*)d_in[4];
    const float* bq    = (const float*)d_in[5];
    const float* Wk    = (const float*)d_in[6];
    const float* bk    = (const float*)d_in[7];
    const float* Wv    = (const float*)d_in[8];
    const float* bv    = (const float*)d_in[9];
    const float* Wh    = (const float*)d_in[10];
    const float* bh    = (const float*)d_in[11];
    const float* Wo    = (const float*)d_in[12];
    const float* bo    = (const float*)d_in[13];
    float* out = (float*)d_out;

    cudaFuncSetAttribute(conv_hmma_kernel, cudaFuncAttributeMaxDynamicSharedMemorySize,
                         NSTAGE * STAGE);

    tconv_kernel<<<(int)(((size_t)NPOS * Uu / 4 + 255) / 256), 256>>>(t);
    repack_kernel<<<(MCH * MCH + 255) / 256, 256>>>(Wq, bq, Wk, bk, Wv, bv);
    cmax_init_kernel<<<(Bb * MCH + 255) / 256, 256>>>();
    conv_hmma_kernel<<<dim3(MCH / TN, NPOS / TM), 256, NSTAGE * STAGE>>>();
    logits_kernel<<<Bb * Hh * NSL, 256>>>(gmask, tmask);
    softmax_kernel<<<Bb * Hh, 256>>>(gmask);
    vsum_kernel<<<Bb * Hh * NSL, 256>>>();
    final_kernel<<<dim3(Bb, 4), 512>>>(Wh, bh, Wo, bo, out);
}